// round 3
// baseline (speedup 1.0000x reference)
#include <cuda_runtime.h>
#include <cuda_bf16.h>

// Problem dims
#define S_ 512
#define B_ 128
#define E_ 100
#define H_ 256
#define T_ 9
#define G_ 1024   // 4*H

// ---------------- scratch (device globals; no allocations) ----------------
__device__ float g_xg[2][S_ * B_ * G_];   // input projections + bias, [dir][s][b][4H]
__device__ float g_h [2][S_ * B_ * H_];   // hidden states, [dir][s][b][H]
__device__ float g_em[B_ * S_ * T_];      // emissions [b][s][t]
__device__ unsigned g_bar[2];             // per-direction step barriers

__device__ __forceinline__ float sigmoidf(float x) { return 1.f / (1.f + expf(-x)); }

// packed fp32x2 FMA (sm_103a FFMA2) — 2 IEEE fp32 FMAs per instruction
__device__ __forceinline__ unsigned long long ffma2(unsigned long long a,
                                                    unsigned long long b,
                                                    unsigned long long c) {
    unsigned long long d;
    asm("fma.rn.f32x2 %0, %1, %2, %3;" : "=l"(d) : "l"(a), "l"(b), "l"(c));
    return d;
}
__device__ __forceinline__ float2 unpack2(unsigned long long v) {
    float2 r;
    asm("mov.b64 {%0, %1}, %2;" : "=f"(r.x), "=f"(r.y) : "l"(v));
    return r;
}
union F4U2 { float4 f4; unsigned long long u2[2]; };

__global__ void reset_kernel() {
    if (threadIdx.x < 2) g_bar[threadIdx.x] = 0u;
}

// ---------------- Kernel A: embed gather + input projection (f32x2) ------
// xg[dir][s][b][g] = sum_k emb[data[b][s]][k] * W_ih[g][k] + bias[g]
// CTA tile: 32 tokens x 128 gates. grid = (2048 token tiles, 16 gate tiles)
// gate tiles 0..7 -> forward, 8..15 -> backward.
// Thread = 4 gates (one float4 of W = 2 gate pairs) x 4 tokens (duplicated X).
__global__ void xg_kernel(const int* __restrict__ data,
                          const float* __restrict__ emb,
                          const float* __restrict__ Wf,
                          const float* __restrict__ bf,
                          const float* __restrict__ Wb,
                          const float* __restrict__ bb) {
    extern __shared__ float sm[];
    float* Xsm = sm;          // [100][72]  32 tokens duplicated (64) + pad
    float* Wsm = sm + 7200;   // [100][132] 128 gates + pad

    int tt  = blockIdx.x;
    int gt  = blockIdx.y;
    int dir = gt >> 3;
    int g0  = (gt & 7) * 128;
    const float* W    = dir ? Wb : Wf;
    const float* bias = dir ? bb : bf;

    // stage X tile (embedding gather), transposed + duplicated: [k][tok*2]
    for (int idx = threadIdx.x; idx < 32 * E_; idx += 256) {
        int j = idx / E_, k = idx - j * E_;
        int tok = tt * 32 + j;            // tok = s*128 + b
        int s = tok >> 7, b = tok & 127;
        int row = data[b * S_ + s];       // 0 => emb row is all zeros
        float v = emb[row * E_ + k];
        *(float2*)&Xsm[k * 72 + j * 2] = make_float2(v, v);
    }
    // stage W tile, transposed [k][gate]
    for (int idx = threadIdx.x; idx < 128 * E_; idx += 256) {
        int r = idx / E_, k = idx - r * E_;
        Wsm[k * 132 + r] = W[(g0 + r) * E_ + k];
    }
    __syncthreads();

    int gg = threadIdx.x & 31;   // 32 gate groups x 4 gates
    int tq = threadIdx.x >> 5;   // 8 token quads x 4 tokens
    unsigned long long a01[4] = {0,0,0,0};  // gate pair (g0,g1) per token
    unsigned long long a23[4] = {0,0,0,0};  // gate pair (g2,g3) per token

    const float* wp = &Wsm[gg * 4];
    const float* xp = &Xsm[tq * 8];
#pragma unroll 4
    for (int k = 0; k < E_; k++) {
        F4U2 w;  w.f4  = *(const float4*)(wp + k * 132);
        F4U2 xA; xA.f4 = *(const float4*)(xp + k * 72);       // (t0,t0,t1,t1)
        F4U2 xB; xB.f4 = *(const float4*)(xp + k * 72 + 4);   // (t2,t2,t3,t3)
        a01[0] = ffma2(w.u2[0], xA.u2[0], a01[0]);
        a23[0] = ffma2(w.u2[1], xA.u2[0], a23[0]);
        a01[1] = ffma2(w.u2[0], xA.u2[1], a01[1]);
        a23[1] = ffma2(w.u2[1], xA.u2[1], a23[1]);
        a01[2] = ffma2(w.u2[0], xB.u2[0], a01[2]);
        a23[2] = ffma2(w.u2[1], xB.u2[0], a23[2]);
        a01[3] = ffma2(w.u2[0], xB.u2[1], a01[3]);
        a23[3] = ffma2(w.u2[1], xB.u2[1], a23[3]);
    }

    float b0v = bias[g0 + gg * 4 + 0];
    float b1v = bias[g0 + gg * 4 + 1];
    float b2v = bias[g0 + gg * 4 + 2];
    float b3v = bias[g0 + gg * 4 + 3];
#pragma unroll
    for (int ti = 0; ti < 4; ti++) {
        int tok = tt * 32 + tq * 4 + ti;
        float2 v01 = unpack2(a01[ti]);
        float2 v23 = unpack2(a23[ti]);
        float4 o = make_float4(v01.x + b0v, v01.y + b1v, v23.x + b2v, v23.y + b3v);
        *(float4*)&g_xg[dir][tok * G_ + g0 + gg * 4] = o;
    }
}

// ---------------- Kernel B: persistent bidirectional LSTM (f32x2) --------
// 128 CTAs x 128 threads. CTAs [0,64): forward, [64,128): backward.
// Per direction: CTA = (32-batch tile) x (16-unit tile = 64 gate rows).
// Thread = 1 unit x 4 gates x 4 batches.
// W slice resident in SMEM (float4 = gate pairs (i,f),(g,o)); h staged each
// step transposed AND duplicated so inner loop = 3x LDS.128 + 8x FFMA2.
__global__ void __launch_bounds__(128, 1)
lstm_kernel(const float* __restrict__ Whhf, const float* __restrict__ Whhb) {
    extern __shared__ float sm[];
    float* Wsm = sm;              // [256][68]: [k][unit*4+gate]
    float* Hsm = sm + 256 * 68;   // [256][68]: [k][b_local*2] duplicated

    int dir = blockIdx.x >> 6;
    int cid = blockIdx.x & 63;
    int b0  = (cid & 3) * 32;
    int u0  = (cid >> 2) * 16;
    const float* Whh = dir ? Whhb : Whhf;

    // stage W slice: rows {gate*256 + u0+unit}
    for (int idx = threadIdx.x; idx < 64 * 256; idx += 128) {
        int r = idx >> 8, k = idx & 255;
        int unit = r >> 2, gate = r & 3;
        Wsm[k * 68 + unit * 4 + gate] = Whh[(gate * 256 + u0 + unit) * 256 + k];
    }

    int un   = threadIdx.x & 15;   // local unit
    int quad = threadIdx.x >> 4;   // 8 batch quads
    int u  = u0 + un;
    int bq = b0 + quad * 4;
    float c[4] = {0.f, 0.f, 0.f, 0.f};
    volatile unsigned* bar = &g_bar[dir];

    const float* wp  = &Wsm[un * 4];
    const float* hp2 = &Hsm[quad * 8];

    for (int ts = 0; ts < S_; ts++) {
        int t = dir ? (S_ - 1 - ts) : ts;

        // prefetch xg for this step (independent of barrier-gated h data)
        const float* xg = &g_xg[dir][(t * B_) * G_];
        float xv[4][4];
#pragma unroll
        for (int j = 0; j < 4; j++)
#pragma unroll
            for (int gate = 0; gate < 4; gate++)
                xv[gate][j] = xg[(bq + j) * G_ + gate * 256 + u];

        unsigned long long aif[4] = {0,0,0,0};  // (i,f) per batch
        unsigned long long ago[4] = {0,0,0,0};  // (g,o) per batch

        if (ts > 0) {
            int tp = dir ? (t + 1) : (t - 1);
            // stage h_prev (our 32 batches) transposed + duplicated
            const float* hp = &g_h[dir][(tp * B_) * H_];
            for (int idx = threadIdx.x; idx < 32 * 64; idx += 128) {
                int j = idx >> 6;   // local batch
                int q = idx & 63;   // unit quad
                float4 hv = *(const float4*)&hp[(b0 + j) * H_ + q * 4];
                *(float2*)&Hsm[(q * 4 + 0) * 68 + j * 2] = make_float2(hv.x, hv.x);
                *(float2*)&Hsm[(q * 4 + 1) * 68 + j * 2] = make_float2(hv.y, hv.y);
                *(float2*)&Hsm[(q * 4 + 2) * 68 + j * 2] = make_float2(hv.z, hv.z);
                *(float2*)&Hsm[(q * 4 + 3) * 68 + j * 2] = make_float2(hv.w, hv.w);
            }
            __syncthreads();

#pragma unroll 4
            for (int k = 0; k < H_; k++) {
                F4U2 w;  w.f4  = *(const float4*)(wp + k * 68);       // (wi,wf,wg,wo)
                F4U2 hA; hA.f4 = *(const float4*)(hp2 + k * 68);      // (h0,h0,h1,h1)
                F4U2 hB; hB.f4 = *(const float4*)(hp2 + k * 68 + 4);  // (h2,h2,h3,h3)
                aif[0] = ffma2(w.u2[0], hA.u2[0], aif[0]);
                ago[0] = ffma2(w.u2[1], hA.u2[0], ago[0]);
                aif[1] = ffma2(w.u2[0], hA.u2[1], aif[1]);
                ago[1] = ffma2(w.u2[1], hA.u2[1], ago[1]);
                aif[2] = ffma2(w.u2[0], hB.u2[0], aif[2]);
                ago[2] = ffma2(w.u2[1], hB.u2[0], ago[2]);
                aif[3] = ffma2(w.u2[0], hB.u2[1], aif[3]);
                ago[3] = ffma2(w.u2[1], hB.u2[1], ago[3]);
            }
        }

        float* hout = &g_h[dir][(t * B_) * H_];
#pragma unroll
        for (int j = 0; j < 4; j++) {
            float2 vif = unpack2(aif[j]);
            float2 vgo = unpack2(ago[j]);
            float ai = vif.x + xv[0][j];
            float af = vif.y + xv[1][j];
            float ag = vgo.x + xv[2][j];
            float ao = vgo.y + xv[3][j];
            c[j] = sigmoidf(af) * c[j] + sigmoidf(ai) * tanhf(ag);
            hout[(bq + j) * H_ + u] = sigmoidf(ao) * tanhf(c[j]);
        }

        // chip-wide (per-direction) step barrier: monotonic counter
        __threadfence();
        __syncthreads();
        if (threadIdx.x == 0) {
            atomicAdd((unsigned*)&g_bar[dir], 1u);
            unsigned target = 64u * (unsigned)(ts + 1);
            while (*bar < target) { }
            __threadfence();
        }
        __syncthreads();
    }
}

// ---------------- Kernel C: MLP emissions ----------------
__global__ void mlp_kernel(const float* __restrict__ mlpW,
                           const float* __restrict__ mlpb) {
    __shared__ float Wsm[T_ * 2 * H_];  // 9*512 floats
    for (int i = threadIdx.x; i < T_ * 2 * H_; i += 256) Wsm[i] = mlpW[i];
    __syncthreads();

    int w = threadIdx.x >> 5, lane = threadIdx.x & 31;
    int tok = blockIdx.x * 8 + w;       // tok = s*128 + b
    int s = tok >> 7, b = tok & 127;

    float acc[T_];
#pragma unroll
    for (int t = 0; t < T_; t++) acc[t] = 0.f;

    const float* hf = &g_h[0][(s * B_ + b) * H_];
    const float* hb = &g_h[1][(s * B_ + b) * H_];
    for (int h = lane; h < H_; h += 32) {
        float v1 = hf[h];
        float v2 = hb[h];
#pragma unroll
        for (int t = 0; t < T_; t++) {
            acc[t] += v1 * Wsm[t * 512 + h];
            acc[t] += v2 * Wsm[t * 512 + 256 + h];
        }
    }
#pragma unroll
    for (int t = 0; t < T_; t++)
        for (int off = 16; off; off >>= 1)
            acc[t] += __shfl_xor_sync(0xFFFFFFFFu, acc[t], off);
    if (lane < T_)
        g_em[(b * S_ + s) * T_ + lane] = acc[lane] + mlpb[lane];
}

// ---------------- Kernel D: CRF Viterbi (one warp per batch) -------------
// Backpointers live in SMEM: forward pass writes them, backtrace reads them
// (29-cyc LDS instead of serial L2 round trips).
__global__ void viterbi_kernel(const int* __restrict__ data,
                               const float* __restrict__ stt,
                               const float* __restrict__ trn,
                               const float* __restrict__ ett,
                               float* __restrict__ out) {
    __shared__ int sbp[2][S_][10];      // [warp][t][tag], padded to 10
    int w = threadIdx.x >> 5, lane = threadIdx.x & 31;
    int b = blockIdx.x * 2 + w;
    int cc = lane < T_ ? lane : (T_ - 1);

    // sequence length = count of nonzero tokens (contiguous prefix)
    int cnt = 0;
    for (int s = lane; s < S_; s += 32) cnt += (data[b * S_ + s] != 0);
    for (int off = 16; off; off >>= 1) cnt += __shfl_xor_sync(0xFFFFFFFFu, cnt, off);
    int len = cnt;

    float tr[T_];
#pragma unroll
    for (int p = 0; p < T_; p++) tr[p] = trn[p * T_ + cc];

    float score = stt[cc] + g_em[(b * S_ + 0) * T_ + cc];

    for (int t = 1; t < S_; t++) {
        float e = g_em[(b * S_ + t) * T_ + cc];
        float best = -1e30f; int bp = 0;
#pragma unroll
        for (int p = 0; p < T_; p++) {
            float sp = __shfl_sync(0xFFFFFFFFu, score, p);
            float cand = sp + tr[p] + e;
            if (cand > best) { best = cand; bp = p; }   // first-max tie-break
        }
        if (lane < T_) sbp[w][t][lane] = bp;
        if (t < len) score = best;
    }

    float fin = score + ett[cc];
    float bestf = -1e30f; int tag = 0;
#pragma unroll
    for (int p = 0; p < T_; p++) {
        float v = __shfl_sync(0xFFFFFFFFu, fin, p);
        if (v > bestf) { bestf = v; tag = p; }
    }
    if (lane == 0) out[B_ * S_ + b] = bestf;

    if (lane == 0) out[b * S_ + (S_ - 1)] = ((S_ - 1) < len) ? (float)tag : 0.f;
    for (int s2 = S_ - 2; s2 >= 0; s2--) {
        int bpv = sbp[w][s2 + 1][cc];
        int prev = __shfl_sync(0xFFFFFFFFu, bpv, tag);
        if (s2 + 1 < len) tag = prev;
        if (lane == 0) out[b * S_ + s2] = (s2 < len) ? (float)tag : 0.f;
    }
}

// ---------------- launch ----------------
extern "C" void kernel_launch(void* const* d_in, const int* in_sizes, int n_in,
                              void* d_out, int out_size) {
    const int*   data = (const int*)d_in[0];
    // d_in[1] = mask (ignored; mask == (data != 0))
    const float* emb  = (const float*)d_in[2];
    const float* Wihf = (const float*)d_in[3];
    const float* Whhf = (const float*)d_in[4];
    const float* bf   = (const float*)d_in[5];
    const float* Wihb = (const float*)d_in[6];
    const float* Whhb = (const float*)d_in[7];
    const float* bb   = (const float*)d_in[8];
    const float* mlpW = (const float*)d_in[9];
    const float* mlpb = (const float*)d_in[10];
    const float* stt  = (const float*)d_in[11];
    const float* trn  = (const float*)d_in[12];
    const float* ett  = (const float*)d_in[13];
    float* out = (float*)d_out;

    cudaFuncSetAttribute(xg_kernel,   cudaFuncAttributeMaxDynamicSharedMemorySize, 81600);
    cudaFuncSetAttribute(lstm_kernel, cudaFuncAttributeMaxDynamicSharedMemorySize, 139264);

    reset_kernel<<<1, 32>>>();
    dim3 gA(2048, 16);
    xg_kernel<<<gA, 256, 81600>>>(data, emb, Wihf, bf, Wihb, bb);
    lstm_kernel<<<128, 128, 139264>>>(Whhf, Whhb);
    mlp_kernel<<<8192, 256>>>(mlpW, mlpb);
    viterbi_kernel<<<64, 64>>>(data, stt, trn, ett, out);
}

// round 4
// speedup vs baseline: 1.1545x; 1.1545x over previous
#include <cuda_runtime.h>
#include <cuda_bf16.h>

// Problem dims
#define S_ 512
#define B_ 128
#define E_ 100
#define H_ 256
#define T_ 9
#define G_ 1024   // 4*H

// ---------------- scratch (device globals; no allocations) ----------------
__device__ float g_xg[2][S_ * B_ * G_];   // input projections + bias, [dir][s][b][4H]
__device__ float g_hT[2][S_ * H_ * B_];   // hidden states TRANSPOSED [dir][s][unit][batch]
__device__ float g_em[B_ * S_ * T_];      // emissions [b][s][t]
__device__ unsigned g_bar2[2][4];         // per-(dir, batch-tile) step barriers

__device__ __forceinline__ float fsig(float x) {
    return __fdividef(1.f, 1.f + __expf(-x));
}
__device__ __forceinline__ float ftanh(float x) {
    return __fdividef(2.f, 1.f + __expf(-2.f * x)) - 1.f;
}

// packed fp32x2 FMA (sm_103a FFMA2) — 2 IEEE fp32 FMAs per instruction
__device__ __forceinline__ unsigned long long ffma2(unsigned long long a,
                                                    unsigned long long b,
                                                    unsigned long long c) {
    unsigned long long d;
    asm("fma.rn.f32x2 %0, %1, %2, %3;" : "=l"(d) : "l"(a), "l"(b), "l"(c));
    return d;
}
__device__ __forceinline__ float2 unpack2(unsigned long long v) {
    float2 r;
    asm("mov.b64 {%0, %1}, %2;" : "=f"(r.x), "=f"(r.y) : "l"(v));
    return r;
}
union F4U2 { float4 f4; unsigned long long u2[2]; };

__global__ void reset_kernel() {
    if (threadIdx.x < 8) ((unsigned*)g_bar2)[threadIdx.x] = 0u;
}

// ---------------- Kernel A: embed gather + input projection (R1 version) -
__global__ void xg_kernel(const int* __restrict__ data,
                          const float* __restrict__ emb,
                          const float* __restrict__ Wf,
                          const float* __restrict__ bf,
                          const float* __restrict__ Wb,
                          const float* __restrict__ bb) {
    extern __shared__ float sm[];
    float* Xsm = sm;          // [100][36]
    float* Wsm = sm + 3600;   // [100][132]

    int tt  = blockIdx.x;
    int gt  = blockIdx.y;
    int dir = gt >> 3;
    int g0  = (gt & 7) * 128;
    const float* W    = dir ? Wb : Wf;
    const float* bias = dir ? bb : bf;

    for (int idx = threadIdx.x; idx < 32 * E_; idx += 256) {
        int j = idx / E_, k = idx - j * E_;
        int tok = tt * 32 + j;            // tok = s*128 + b
        int s = tok >> 7, b = tok & 127;
        int row = data[b * S_ + s];
        Xsm[k * 36 + j] = emb[row * E_ + k];
    }
    for (int idx = threadIdx.x; idx < 128 * E_; idx += 256) {
        int r = idx / E_, k = idx - r * E_;
        Wsm[k * 132 + r] = W[(g0 + r) * E_ + k];
    }
    __syncthreads();

    int gg = threadIdx.x & 31;
    int tg = threadIdx.x >> 5;
    float acc[4][4];
#pragma unroll
    for (int i = 0; i < 4; i++)
#pragma unroll
        for (int j = 0; j < 4; j++) acc[i][j] = 0.f;

    const float* wp = &Wsm[gg * 4];
    const float* xp = &Xsm[tg * 4];
    for (int k = 0; k < E_; k++) {
        float4 w = *(const float4*)(wp + k * 132);
        float4 x = *(const float4*)(xp + k * 36);
        acc[0][0] += w.x * x.x; acc[0][1] += w.x * x.y; acc[0][2] += w.x * x.z; acc[0][3] += w.x * x.w;
        acc[1][0] += w.y * x.x; acc[1][1] += w.y * x.y; acc[1][2] += w.y * x.z; acc[1][3] += w.y * x.w;
        acc[2][0] += w.z * x.x; acc[2][1] += w.z * x.y; acc[2][2] += w.z * x.z; acc[2][3] += w.z * x.w;
        acc[3][0] += w.w * x.x; acc[3][1] += w.w * x.y; acc[3][2] += w.w * x.z; acc[3][3] += w.w * x.w;
    }

    float b0v = bias[g0 + gg * 4 + 0];
    float b1v = bias[g0 + gg * 4 + 1];
    float b2v = bias[g0 + gg * 4 + 2];
    float b3v = bias[g0 + gg * 4 + 3];
#pragma unroll
    for (int ti = 0; ti < 4; ti++) {
        int tok = tt * 32 + tg * 4 + ti;
        float4 o = make_float4(acc[0][ti] + b0v, acc[1][ti] + b1v,
                               acc[2][ti] + b2v, acc[3][ti] + b3v);
        *(float4*)&g_xg[dir][tok * G_ + g0 + gg * 4] = o;
    }
}

// ---------------- Kernel B: persistent bidirectional LSTM ----------------
// 128 CTAs x 256 threads (8 warps). CTAs [0,64): fwd, [64,128): bwd.
// CTA = 32-batch tile x 16-unit tile. Thread = 1 unit x 4 gates x 2 batches
// (gate-packed FFMA2). Warp spans 8 units x 4 batch-pairs (min smem traffic).
// W resident in SMEM; h staged transposed+duplicated per step.
// Sync domain: 16 CTAs sharing (dir, batch tile).
__global__ void __launch_bounds__(256, 1)
lstm_kernel(const float* __restrict__ Whhf, const float* __restrict__ Whhb) {
    extern __shared__ float sm[];
    float* Wsm = sm;              // [256][68]: [k][unit*4 + gate]
    float* Hsm = sm + 256 * 68;   // [256][68]: [k][bg*4] = (hA,hA,hB,hB)

    int dir   = blockIdx.x >> 6;
    int cid   = blockIdx.x & 63;
    int btile = cid & 3;
    int b0    = btile * 32;
    int u0    = (cid >> 2) * 16;
    const float* Whh = dir ? Whhb : Whhf;

    // stage W slice: rows {gate*256 + u0+unit}
    for (int idx = threadIdx.x; idx < 64 * 256; idx += 256) {
        int r = idx >> 8, k = idx & 255;
        int unit = r >> 2, gate = r & 3;
        Wsm[k * 68 + unit * 4 + gate] = Whh[(gate * 256 + u0 + unit) * 256 + k];
    }

    int lane = threadIdx.x & 31;
    int w    = threadIdx.x >> 5;
    int un = (lane & 7) + (w & 1) * 8;          // 0..15
    int bg = (lane >> 3) + (w >> 1) * 4;        // 0..15 batch pairs
    int u  = u0 + un;
    int bA = b0 + bg * 2, bB = bA + 1;
    float cA = 0.f, cB = 0.f;
    volatile unsigned* bar = &g_bar2[dir][btile];

    const float* wp = &Wsm[un * 4];
    const float* hp2 = &Hsm[bg * 4];

    for (int ts = 0; ts < S_; ts++) {
        int t = dir ? (S_ - 1 - ts) : ts;

        // prefetch xg (independent of barrier-gated h)
        const float* xg = &g_xg[dir][(t * B_) * G_];
        float xvA[4], xvB[4];
#pragma unroll
        for (int gate = 0; gate < 4; gate++) {
            xvA[gate] = xg[bA * G_ + gate * 256 + u];
            xvB[gate] = xg[bB * G_ + gate * 256 + u];
        }

        unsigned long long aifA = 0, agoA = 0, aifB = 0, agoB = 0;

        if (ts > 0) {
            int tp = dir ? (t + 1) : (t - 1);
            // stage h_prev from transposed gmem [unit][batch] -> dup SMEM
            const float* hp = &g_hT[dir][(tp * H_) * B_];
            for (int idx = threadIdx.x; idx < 2048; idx += 256) {
                int k  = idx >> 3;       // unit
                int bq = idx & 7;        // 4-batch group
                float4 hv = *(const float4*)&hp[k * B_ + b0 + bq * 4];
                float* dst = &Hsm[k * 68 + bq * 8];
                *(float4*)(dst)     = make_float4(hv.x, hv.x, hv.y, hv.y);
                *(float4*)(dst + 4) = make_float4(hv.z, hv.z, hv.w, hv.w);
            }
            __syncthreads();

#pragma unroll 8
            for (int k = 0; k < H_; k++) {
                F4U2 wv; wv.f4 = *(const float4*)(wp  + k * 68);   // (wi,wf,wg,wo)
                F4U2 hv; hv.f4 = *(const float4*)(hp2 + k * 68);   // (hA,hA,hB,hB)
                aifA = ffma2(wv.u2[0], hv.u2[0], aifA);
                agoA = ffma2(wv.u2[1], hv.u2[0], agoA);
                aifB = ffma2(wv.u2[0], hv.u2[1], aifB);
                agoB = ffma2(wv.u2[1], hv.u2[1], agoB);
            }
        }

        float2 vifA = unpack2(aifA), vgoA = unpack2(agoA);
        float2 vifB = unpack2(aifB), vgoB = unpack2(agoB);

        float aiA = vifA.x + xvA[0], afA = vifA.y + xvA[1];
        float agA = vgoA.x + xvA[2], aoA = vgoA.y + xvA[3];
        cA = fsig(afA) * cA + fsig(aiA) * ftanh(agA);
        float hA = fsig(aoA) * ftanh(cA);

        float aiB = vifB.x + xvB[0], afB = vifB.y + xvB[1];
        float agB = vgoB.x + xvB[2], aoB = vgoB.y + xvB[3];
        cB = fsig(afB) * cB + fsig(aiB) * ftanh(agB);
        float hB = fsig(aoB) * ftanh(cB);

        // transposed store: g_hT[dir][t][u][bA..bB]
        *(float2*)&g_hT[dir][(t * H_ + u) * B_ + bA] = make_float2(hA, hB);

        // group barrier (16 CTAs sharing this dir+batch tile)
        __threadfence();
        __syncthreads();
        if (threadIdx.x == 0) {
            atomicAdd((unsigned*)&g_bar2[dir][btile], 1u);
            unsigned target = 16u * (unsigned)(ts + 1);
            while (*bar < target) { }
            __threadfence();
        }
        __syncthreads();
    }
}

// ---------------- Kernel C: MLP emissions (transposed h layout) ----------
// CTA per s (512 CTAs), 128 threads, thread = one batch b.
__global__ void mlp_kernel(const float* __restrict__ mlpW,
                           const float* __restrict__ mlpb) {
    __shared__ float Wsm[T_ * 2 * H_];  // 9*512 floats
    for (int i = threadIdx.x; i < T_ * 2 * H_; i += 128) Wsm[i] = mlpW[i];
    __syncthreads();

    int s = blockIdx.x;
    int b = threadIdx.x;

    float acc[T_];
#pragma unroll
    for (int t = 0; t < T_; t++) acc[t] = 0.f;

    const float* hf = &g_hT[0][(s * H_) * B_ + b];
    const float* hb = &g_hT[1][(s * H_) * B_ + b];
#pragma unroll 4
    for (int k = 0; k < H_; k++) {
        float v1 = hf[k * B_];
        float v2 = hb[k * B_];
#pragma unroll
        for (int t = 0; t < T_; t++) {
            acc[t] += v1 * Wsm[t * 512 + k];
            acc[t] += v2 * Wsm[t * 512 + 256 + k];
        }
    }
#pragma unroll
    for (int t = 0; t < T_; t++)
        g_em[(b * S_ + s) * T_ + t] = acc[t] + mlpb[t];
}

// ---------------- Kernel D: CRF Viterbi (one warp per batch) -------------
__global__ void viterbi_kernel(const int* __restrict__ data,
                               const float* __restrict__ stt,
                               const float* __restrict__ trn,
                               const float* __restrict__ ett,
                               float* __restrict__ out) {
    __shared__ int sbp[2][S_][10];
    int w = threadIdx.x >> 5, lane = threadIdx.x & 31;
    int b = blockIdx.x * 2 + w;
    int cc = lane < T_ ? lane : (T_ - 1);

    int cnt = 0;
    for (int s = lane; s < S_; s += 32) cnt += (data[b * S_ + s] != 0);
    for (int off = 16; off; off >>= 1) cnt += __shfl_xor_sync(0xFFFFFFFFu, cnt, off);
    int len = cnt;

    float tr[T_];
#pragma unroll
    for (int p = 0; p < T_; p++) tr[p] = trn[p * T_ + cc];

    float score = stt[cc] + g_em[(b * S_ + 0) * T_ + cc];

    for (int t = 1; t < S_; t++) {
        float e = g_em[(b * S_ + t) * T_ + cc];
        float best = -1e30f; int bp = 0;
#pragma unroll
        for (int p = 0; p < T_; p++) {
            float sp = __shfl_sync(0xFFFFFFFFu, score, p);
            float cand = sp + tr[p] + e;
            if (cand > best) { best = cand; bp = p; }   // first-max tie-break
        }
        if (lane < T_) sbp[w][t][lane] = bp;
        if (t < len) score = best;
    }

    float fin = score + ett[cc];
    float bestf = -1e30f; int tag = 0;
#pragma unroll
    for (int p = 0; p < T_; p++) {
        float v = __shfl_sync(0xFFFFFFFFu, fin, p);
        if (v > bestf) { bestf = v; tag = p; }
    }
    if (lane == 0) out[B_ * S_ + b] = bestf;

    if (lane == 0) out[b * S_ + (S_ - 1)] = ((S_ - 1) < len) ? (float)tag : 0.f;
    for (int s2 = S_ - 2; s2 >= 0; s2--) {
        int bpv = sbp[w][s2 + 1][cc];
        int prev = __shfl_sync(0xFFFFFFFFu, bpv, tag);
        if (s2 + 1 < len) tag = prev;
        if (lane == 0) out[b * S_ + s2] = (s2 < len) ? (float)tag : 0.f;
    }
}

// ---------------- launch ----------------
extern "C" void kernel_launch(void* const* d_in, const int* in_sizes, int n_in,
                              void* d_out, int out_size) {
    const int*   data = (const int*)d_in[0];
    // d_in[1] = mask (ignored; mask == (data != 0))
    const float* emb  = (const float*)d_in[2];
    const float* Wihf = (const float*)d_in[3];
    const float* Whhf = (const float*)d_in[4];
    const float* bf   = (const float*)d_in[5];
    const float* Wihb = (const float*)d_in[6];
    const float* Whhb = (const float*)d_in[7];
    const float* bb   = (const float*)d_in[8];
    const float* mlpW = (const float*)d_in[9];
    const float* mlpb = (const float*)d_in[10];
    const float* stt  = (const float*)d_in[11];
    const float* trn  = (const float*)d_in[12];
    const float* ett  = (const float*)d_in[13];
    float* out = (float*)d_out;

    cudaFuncSetAttribute(xg_kernel,   cudaFuncAttributeMaxDynamicSharedMemorySize, 67200);
    cudaFuncSetAttribute(lstm_kernel, cudaFuncAttributeMaxDynamicSharedMemorySize, 139264);

    reset_kernel<<<1, 32>>>();
    dim3 gA(2048, 16);
    xg_kernel<<<gA, 256, 67200>>>(data, emb, Wihf, bf, Wihb, bb);
    lstm_kernel<<<128, 256, 139264>>>(Whhf, Whhb);
    mlp_kernel<<<512, 128>>>(mlpW, mlpb);
    viterbi_kernel<<<64, 64>>>(data, stt, trn, ett, out);
}